// round 10
// baseline (speedup 1.0000x reference)
#include <cuda_runtime.h>
#include <cuda_fp16.h>

// FastPooling "social", 2-phase:
//  K1: H[j][cc][:] = hidden[j] @ W[:,cc,:] via mma.m16n8k8.tf32 straight from
//      fp32 inputs (cvt.rna.tf32 at staging), fp32 accum, fp16 store -> g_Hh.
//  K2 (fused): per ped i - winner scatter (shared atomicMax, last-write-wins
//      == max-j; out-of-range peds write zeros to cell 0 -> in_range bit
//      suppresses), in-smem compaction, branch-free MLP-8 gather, bias+relu.

#define N_MAX   512
#define HID     128
#define GRID_S  32
#define NCELLS  (GRID_S * GRID_S)   // 1024
#define CC_N    16
#define OUTD    128
#define BM      64
#define LDW     132                  // padded fp32 leading dim (words)

__device__ __half g_Hh[N_MAX * CC_N * OUTD];         // 2 MB fp16 H

__device__ __forceinline__ unsigned tf32(float f) {
    unsigned u; asm("cvt.rna.tf32.f32 %0, %1;" : "=r"(u) : "f"(f)); return u;
}
__device__ __forceinline__ void mma_tf32(float d[4], const unsigned a[4],
                                         unsigned b0, unsigned b1) {
    asm volatile("mma.sync.aligned.m16n8k8.row.col.f32.tf32.tf32.f32 "
                 "{%0,%1,%2,%3}, {%4,%5,%6,%7}, {%8,%9}, {%0,%1,%2,%3};"
                 : "+f"(d[0]), "+f"(d[1]), "+f"(d[2]), "+f"(d[3])
                 : "r"(a[0]), "r"(a[1]), "r"(a[2]), "r"(a[3]), "r"(b0), "r"(b1));
}
__device__ __forceinline__ unsigned cvt2h(float a, float b) {
    __half2 h = __floats2half2_rn(a, b);
    return *reinterpret_cast<unsigned*>(&h);
}

// ---------------------------------------------------------------------------
// K1: tf32 HMMA GEMM, block = 64 rows x 128 cols (one cc). Grid (n/64,16)=128.
// Dynamic smem: sA[64][LDW] + sB[128][LDW] (tf32 bits) = ~99 KB.
// ---------------------------------------------------------------------------
__global__ __launch_bounds__(256) void gemm1_tf32_kernel(
    const float* __restrict__ hidden,
    const float* __restrict__ W,
    int n)
{
    extern __shared__ unsigned smem[];
    unsigned* sA = smem;                 // [64][LDW]
    unsigned* sB = smem + BM * LDW;      // [128][LDW]  (k x n)

    const int cc    = blockIdx.y;
    const int jbase = blockIdx.x * BM;
    const int t     = threadIdx.x;

    // stage A: 64 rows x 32 float4 = 2048 float4, 8/thread, coalesced
    #pragma unroll
    for (int s = 0; s < 8; ++s) {
        const int idx  = t + 256 * s;
        const int row  = idx >> 5;
        const int col4 = (idx & 31) * 4;
        float4 f = make_float4(0.f, 0.f, 0.f, 0.f);
        if (jbase + row < n)
            f = *reinterpret_cast<const float4*>(hidden + (size_t)(jbase + row) * HID + col4);
        unsigned* dst = &sA[row * LDW + col4];
        dst[0] = tf32(f.x); dst[1] = tf32(f.y); dst[2] = tf32(f.z); dst[3] = tf32(f.w);
    }
    // stage B: 128 k-rows x 32 float4 = 4096 float4, 16/thread
    #pragma unroll
    for (int s = 0; s < 16; ++s) {
        const int idx  = t + 256 * s;
        const int k    = idx >> 5;
        const int col4 = (idx & 31) * 4;
        const float4 f = *reinterpret_cast<const float4*>(
            W + ((size_t)(k * CC_N + cc)) * OUTD + col4);
        unsigned* dst = &sB[k * LDW + col4];
        dst[0] = tf32(f.x); dst[1] = tf32(f.y); dst[2] = tf32(f.z); dst[3] = tf32(f.w);
    }
    __syncthreads();

    const int wid  = t >> 5;
    const int lane = t & 31;
    const int wc   = wid * 16;          // warp's 16 output cols
    const int r    = lane >> 2;         // group id 0..7
    const int c    = lane & 3;          // thread-in-group 0..3

    float d[4][2][4];
    #pragma unroll
    for (int mt = 0; mt < 4; ++mt)
        #pragma unroll
        for (int nt = 0; nt < 2; ++nt)
            #pragma unroll
            for (int q = 0; q < 4; ++q) d[mt][nt][q] = 0.f;

    #pragma unroll
    for (int ks = 0; ks < 16; ++ks) {
        const int k0 = ks * 8;
        // B frags: b0: row k0+c, col wc+nt*8+r ; b1: row k0+c+4, same col
        unsigned b00 = sB[(k0 + c) * LDW + wc + r];
        unsigned b01 = sB[(k0 + c + 4) * LDW + wc + r];
        unsigned b10 = sB[(k0 + c) * LDW + wc + 8 + r];
        unsigned b11 = sB[(k0 + c + 4) * LDW + wc + 8 + r];
        #pragma unroll
        for (int mt = 0; mt < 4; ++mt) {
            unsigned a[4];
            const unsigned* ar0 = &sA[(mt * 16 + r) * LDW + k0 + c];
            const unsigned* ar1 = &sA[(mt * 16 + r + 8) * LDW + k0 + c];
            a[0] = ar0[0]; a[1] = ar1[0]; a[2] = ar0[4]; a[3] = ar1[4];
            mma_tf32(d[mt][0], a, b00, b01);
            mma_tf32(d[mt][1], a, b10, b11);
        }
    }

    // epilogue: D frag: rows r, r+8; cols 2c, 2c+1 within each 8-col tile
    #pragma unroll
    for (int mt = 0; mt < 4; ++mt) {
        #pragma unroll
        for (int nt = 0; nt < 2; ++nt) {
            const int jg  = jbase + mt * 16 + r;
            const int col = wc + nt * 8 + c * 2;
            const unsigned lo = cvt2h(d[mt][nt][0], d[mt][nt][1]);
            const unsigned hi = cvt2h(d[mt][nt][2], d[mt][nt][3]);
            if (jg < n)
                *reinterpret_cast<unsigned*>(g_Hh + ((size_t)jg * CC_N + cc) * OUTD + col) = lo;
            if (jg + 8 < n)
                *reinterpret_cast<unsigned*>(g_Hh + ((size_t)(jg + 8) * CC_N + cc) * OUTD + col) = hi;
        }
    }
}

// ---------------------------------------------------------------------------
// K2: fused scatter + compact + gather. 128 threads, ~10.5 KB smem.
// ---------------------------------------------------------------------------
__global__ __launch_bounds__(128) void scatter_gather_kernel(
    const float* __restrict__ obs2,
    const float* __restrict__ bias,
    float* __restrict__ out,
    int n)
{
    __shared__ __align__(16) float red[4][OUTD];   // 2 KB
    __shared__ int win[NCELLS];                    // 4 KB
    __shared__ int lst[NCELLS];                    // 4 KB
    __shared__ int cnt;

    const int i    = blockIdx.x;
    const int t    = threadIdx.x;
    const int w    = t >> 5;
    const int lane = t & 31;

    if (t == 0) cnt = 0;
    #pragma unroll
    for (int s = 0; s < 8; ++s) win[t + 128 * s] = -1;

    const float2* obs = reinterpret_cast<const float2*>(obs2);
    const float xi = obs[i].x;
    const float yi = obs[i].y;

    float2 o[4];
    #pragma unroll
    for (int s = 0; s < 4; ++s) {
        const int j = t + 128 * s;
        o[s] = (j < n) ? obs[j] : make_float2(1e9f, 1e9f);
    }
    __syncthreads();

    #pragma unroll
    for (int s = 0; s < 4; ++s) {
        const int j = t + 128 * s;
        const bool act = (j < n) & (j != i);
        const float ox = (o[s].x - xi) * 4.0f + 16.0f;
        const float oy = (o[s].y - yi) * 4.0f + 16.0f;
        const bool inr = (ox >= 0.f) & (ox < 32.f) & (oy >= 0.f) & (oy < 32.f);
        const int cell = inr ? (((int)ox) * GRID_S + (int)oy) : 0;
        if (act) atomicMax(&win[cell], (j << 1) | (inr ? 1 : 0));
    }
    __syncthreads();

    #pragma unroll
    for (int base_c = 0; base_c < NCELLS; base_c += 128) {
        const int c   = base_c + t;
        const int enc = win[c];
        const bool valid = (enc >= 0) && (enc & 1);
        const unsigned mask = __ballot_sync(0xffffffffu, valid);
        if (mask) {
            const int leader = __ffs(mask) - 1;
            int base = 0;
            if (lane == leader) base = atomicAdd(&cnt, __popc(mask));
            base = __shfl_sync(0xffffffffu, base, leader);
            if (valid) {
                const int j  = enc >> 1;
                const int cc = (c >> 8) * 4 + ((c >> 3) & 3);
                lst[base + __popc(mask & ((1u << lane) - 1u))] = j * CC_N + cc;
            }
        }
    }
    __syncthreads();
    const int m = cnt;

    float4 acc0 = make_float4(0.f, 0.f, 0.f, 0.f);
    float4 acc1 = make_float4(0.f, 0.f, 0.f, 0.f);
    const int co = lane * 4;

    #define ACCUM(A, u) do {                                              \
        const __half2 _h0 = *reinterpret_cast<const __half2*>(&(u).x);    \
        const __half2 _h1 = *reinterpret_cast<const __half2*>(&(u).y);    \
        const float2 _f0 = __half22float2(_h0);                           \
        const float2 _f1 = __half22float2(_h1);                           \
        A.x += _f0.x; A.y += _f0.y; A.z += _f1.x; A.w += _f1.y;           \
    } while (0)

    int e = w;
    for (; e + 28 < m; e += 32) {
        const int p0 = lst[e];      const int p1 = lst[e + 4];
        const int p2 = lst[e + 8];  const int p3 = lst[e + 12];
        const int p4 = lst[e + 16]; const int p5 = lst[e + 20];
        const int p6 = lst[e + 24]; const int p7 = lst[e + 28];
        const uint2 v0 = *reinterpret_cast<const uint2*>(g_Hh + (size_t)p0 * OUTD + co);
        const uint2 v1 = *reinterpret_cast<const uint2*>(g_Hh + (size_t)p1 * OUTD + co);
        const uint2 v2 = *reinterpret_cast<const uint2*>(g_Hh + (size_t)p2 * OUTD + co);
        const uint2 v3 = *reinterpret_cast<const uint2*>(g_Hh + (size_t)p3 * OUTD + co);
        const uint2 v4 = *reinterpret_cast<const uint2*>(g_Hh + (size_t)p4 * OUTD + co);
        const uint2 v5 = *reinterpret_cast<const uint2*>(g_Hh + (size_t)p5 * OUTD + co);
        const uint2 v6 = *reinterpret_cast<const uint2*>(g_Hh + (size_t)p6 * OUTD + co);
        const uint2 v7 = *reinterpret_cast<const uint2*>(g_Hh + (size_t)p7 * OUTD + co);
        ACCUM(acc0, v0); ACCUM(acc1, v1); ACCUM(acc0, v2); ACCUM(acc1, v3);
        ACCUM(acc0, v4); ACCUM(acc1, v5); ACCUM(acc0, v6); ACCUM(acc1, v7);
    }
    for (; e < m; e += 4) {
        const int p = lst[e];
        const uint2 v = *reinterpret_cast<const uint2*>(g_Hh + (size_t)p * OUTD + co);
        ACCUM(acc0, v);
    }
    #undef ACCUM
    acc0.x += acc1.x; acc0.y += acc1.y; acc0.z += acc1.z; acc0.w += acc1.w;

    *reinterpret_cast<float4*>(&red[w][co]) = acc0;
    __syncthreads();

    if (t < OUTD) {
        float s = bias[t];
        #pragma unroll
        for (int r = 0; r < 4; ++r) s += red[r][t];
        out[(size_t)i * OUTD + t] = fmaxf(s, 0.f);
    }
}

// ---------------------------------------------------------------------------
// inputs: hidden_state (n,128) f32 | obs1 (n,2) (unused) | obs2 (n,2) f32 |
//         W (2048,128) f32 | b (128,) f32   -> out (n,128) f32
// ---------------------------------------------------------------------------
extern "C" void kernel_launch(void* const* d_in, const int* in_sizes, int n_in,
                              void* d_out, int out_size)
{
    const float* hidden = (const float*)d_in[0];
    const float* obs2   = (const float*)d_in[2];
    const float* W      = (const float*)d_in[3];
    const float* bias   = (const float*)d_in[4];
    float*       out    = (float*)d_out;

    const int n = in_sizes[2] / 2;   // 512

    const int smem_bytes = (BM + HID) * LDW * sizeof(unsigned);   // ~99 KB
    cudaFuncSetAttribute(gemm1_tf32_kernel,
                         cudaFuncAttributeMaxDynamicSharedMemorySize, smem_bytes);

    dim3 g1((n + BM - 1) / BM, CC_N);
    gemm1_tf32_kernel<<<g1, 256, smem_bytes>>>(hidden, W, n);
    scatter_gather_kernel<<<n, 128>>>(obs2, bias, out, n);
}